// round 14
// baseline (speedup 1.0000x reference)
#include <cuda_runtime.h>
#include <cuda_fp16.h>
#include <math.h>
#include <stdint.h>

#define DM  256
#define SEQ 2304       // 48*48
#define NB  16

__device__ __half g_Q[NB * SEQ * DM];
__device__ __half g_K[NB * SEQ * DM];
__device__ __half g_V[NB * SEQ * DM];
__device__ __half g_W16[3 * DM * DM];

// ---------------------------------------------------------------------------
// helpers
// ---------------------------------------------------------------------------
__device__ __forceinline__ uint32_t smem_u32(const void* p) {
    uint32_t a;
    asm("{ .reg .u64 t; cvta.to.shared.u64 t, %1; cvt.u32.u64 %0, t; }"
        : "=r"(a) : "l"(p));
    return a;
}
__device__ __forceinline__ void ldsm4(uint32_t* r, uint32_t addr) {
    asm volatile("ldmatrix.sync.aligned.m8n8.x4.shared.b16 {%0,%1,%2,%3}, [%4];"
        : "=r"(r[0]), "=r"(r[1]), "=r"(r[2]), "=r"(r[3]) : "r"(addr));
}
__device__ __forceinline__ void ldsm4t(uint32_t* r, uint32_t addr) {
    asm volatile("ldmatrix.sync.aligned.m8n8.x4.trans.shared.b16 {%0,%1,%2,%3}, [%4];"
        : "=r"(r[0]), "=r"(r[1]), "=r"(r[2]), "=r"(r[3]) : "r"(addr));
}
__device__ __forceinline__ void mma16816(float* c, const uint32_t* a,
                                         uint32_t b0, uint32_t b1) {
    asm volatile(
        "mma.sync.aligned.m16n8k16.row.col.f32.f16.f16.f32 "
        "{%0,%1,%2,%3},{%4,%5,%6,%7},{%8,%9},{%0,%1,%2,%3};"
        : "+f"(c[0]), "+f"(c[1]), "+f"(c[2]), "+f"(c[3])
        : "r"(a[0]), "r"(a[1]), "r"(a[2]), "r"(a[3]), "r"(b0), "r"(b1));
}
__device__ __forceinline__ uint32_t pack_h2(float lo, float hi) {
    uint32_t r;
    asm("cvt.rn.f16x2.f32 %0, %1, %2;" : "=r"(r) : "f"(hi), "f"(lo));
    return r;
}
#define CP_ASYNC16(dst, src) \
    asm volatile("cp.async.cg.shared.global [%0], [%1], 16;" \
                 :: "r"(dst), "l"(src) : "memory")
#define CP_COMMIT() asm volatile("cp.async.commit_group;" ::: "memory")
#define CP_WAIT0()  asm volatile("cp.async.wait_group 0;" ::: "memory")

#define ASTR 528                        // bytes per smem row (256h + 8h pad)

// ---------------------------------------------------------------------------
// W pre-convert (one-time, ~4.4us)
// ---------------------------------------------------------------------------
__global__ __launch_bounds__(256) void wconv(
    const float* __restrict__ wq, const float* __restrict__ wk,
    const float* __restrict__ wv)
{
    int i4 = (blockIdx.x * 256 + threadIdx.x) * 4;
    int wsel = i4 >> 16;
    int off  = i4 & 65535;
    const float* src = (wsel == 0) ? wq : (wsel == 1) ? wk : wv;
    float4 v = *(const float4*)(src + off);
    uint2 u;
    u.x = pack_h2(v.x, v.y);
    u.y = pack_h2(v.z, v.w);
    *(uint2*)(g_W16 + i4) = u;
}

// ---------------------------------------------------------------------------
// QKV v4: grid (288, 3) — one wsel per CTA. W (135 KB fp16) streamed in ONCE
// via cp.async overlapped with A=(x+pos) load; ONE barrier; then 512
// uninterrupted HMMA per warp (K=256 in one sweep); epilogue. No chunk
// barriers, no W double buffering.
// ---------------------------------------------------------------------------
#define QA  0
#define QW  (128 * ASTR)             // 67584
#define QBIA (QW + 256 * ASTR)       // 202752
#define QKV_SMEM (QBIA + 1024)       // 203776

__global__ __launch_bounds__(256, 1) void qkv_v4(
    const float* __restrict__ x,  const float* __restrict__ pos,
    const float* __restrict__ bq, const float* __restrict__ bk,
    const float* __restrict__ bv)
{
    extern __shared__ char smem[];
    const uint32_t sb = smem_u32(smem);
    const int t = threadIdx.x, w = t >> 5, lane = t & 31;
    const int g = lane >> 2, tg = lane & 3;
    const int i8 = lane & 7, s1 = (lane >> 3) & 1, s2 = (lane >> 4) & 1;
    const int q4 = lane >> 3;

    const int m0 = blockIdx.x * 128;
    const int wsel = blockIdx.y;
    const int sbase = m0 % SEQ;

    const float* bias_g = (wsel == 0) ? bq : (wsel == 1) ? bk : bv;
    __half* outp = (wsel == 0) ? g_Q : (wsel == 1) ? g_K : g_V;

    // ---- issue the FULL W tile (256 k-rows) via cp.async ----
    {
        const char* Wsrc = (const char*)(g_W16 + wsel * DM * DM);
        #pragma unroll
        for (int p = 0; p < 32; p++) {
            int q = p * 256 + t;
            int row = q >> 5, gr = q & 31;
            CP_ASYNC16(sb + QW + row * ASTR + gr * 16, Wsrc + row * 512 + gr * 16);
        }
        CP_COMMIT();
    }

    // ---- bias -> smem (256 floats) ----
    if (t < 64) {
        int off = t * 4;
        *(float4*)(smem + QBIA + off * 4) = *(const float4*)(bias_g + off);
    }

    // ---- A = x + pos (fp32 loads, fp16 pack) — overlaps W stream ----
    #pragma unroll
    for (int p = 0; p < 32; p++) {
        int fid = p * 256 + t;
        int row = fid >> 6, c4 = fid & 63;
        float4 xa = *(const float4*)(x   + (size_t)(m0 + row) * DM + c4 * 4);
        float4 pa = *(const float4*)(pos + (size_t)(sbase + row) * DM + c4 * 4);
        uint2 u;
        u.x = pack_h2(xa.x + pa.x, xa.y + pa.y);
        u.y = pack_h2(xa.z + pa.z, xa.w + pa.w);
        *(uint2*)(smem + QA + row * ASTR + c4 * 8) = u;
    }

    CP_WAIT0();
    __syncthreads();     // the ONLY barrier before the epilogue

    const int wm2 = w & 1, wn2 = w >> 1;
    const uint32_t abase = sb + QA + (64 * wm2 + i8 + s1 * 8) * ASTR + s2 * 16;
    const uint32_t wb_lane = (uint32_t)(((q4 & 1) * 8 + i8) * ASTR + (q4 >> 1) * 16
                                        + 128 * wn2);

    float acc[4][8][4] = {};

    // ---- full K=256 sweep: 16 k-steps, 512 HMMA/warp, zero barriers ----
    #pragma unroll
    for (int kk = 0; kk < 16; kk++) {
        uint32_t a[4][4];
        #pragma unroll
        for (int mi = 0; mi < 4; mi++)
            ldsm4(a[mi], abase + mi * 16 * ASTR + kk * 32);
        #pragma unroll
        for (int np = 0; np < 4; np++) {
            uint32_t bb[4];
            ldsm4t(bb, sb + QW + (uint32_t)(kk * 16) * ASTR + wb_lane + np * 32);
            #pragma unroll
            for (int mi = 0; mi < 4; mi++) {
                mma16816(acc[mi][2 * np],     a[mi], bb[0], bb[1]);
                mma16816(acc[mi][2 * np + 1], a[mi], bb[2], bb[3]);
            }
        }
    }

    // ---- epilogue ----
    const float* bias = (const float*)(smem + QBIA);
    #pragma unroll
    for (int mi = 0; mi < 4; mi++) {
        int r0 = 64 * wm2 + 16 * mi + g;
        #pragma unroll
        for (int nt = 0; nt < 8; nt++) {
            int col = 64 * wn2 + 8 * nt + 2 * tg;
            float2 bv2 = *(const float2*)(bias + col);
            *(uint32_t*)(outp + (size_t)(m0 + r0) * DM + col) =
                pack_h2(acc[mi][nt][0] + bv2.x, acc[mi][nt][1] + bv2.y);
            *(uint32_t*)(outp + (size_t)(m0 + r0 + 8) * DM + col) =
                pack_h2(acc[mi][nt][2] + bv2.x, acc[mi][nt][3] + bv2.y);
        }
    }
}

// ---------------------------------------------------------------------------
// Attention (R8/R9, verified 242us): CTA = 128 q rows, 8 warps, TOK = 64.
// S-phase: 4 row-groups(32r) x 2 token-halves(32t); wide ldsm4.
// P (128x64 fp16) roundtrips through smem.
// O-phase: 2 row-groups(64r) x 4 d-slices(64d); wide ldsm4t.
// K and V double-buffered via cp.async. 2 barriers per chunk.
// ---------------------------------------------------------------------------
#define TOK 64
#define NCHUNK (SEQ / TOK)       // 36
#define PSTR 144                 // P row stride (64h=128B + 16 pad)

#define AQ  0                        // Q  [128][528]   67584
#define AK0 (128 * ASTR)             // K buf0 [64][528]
#define AK1 (AK0 + 64 * ASTR)
#define AV0 (AK1 + 64 * ASTR)
#define AV1 (AV0 + 64 * ASTR)
#define AP  (AV1 + 64 * ASTR)        // P [128][144]
#define ARS (AP + 128 * PSTR)
#define ATT_SMEM (ARS + 1024)

__global__ __launch_bounds__(256, 1) void attn_mma(float* __restrict__ out)
{
    extern __shared__ char smem[];
    const uint32_t sb = smem_u32(smem);
    const int t = threadIdx.x, w = t >> 5, lane = t & 31;
    const int g = lane >> 2, tg = lane & 3;
    const int i8 = lane & 7, s1 = (lane >> 3) & 1, s2 = (lane >> 4) & 1;
    const int q4 = lane >> 3;

    const int qt = blockIdx.x, b = blockIdx.y;
    const __half* Qg = g_Q + ((size_t)b * SEQ + qt * 128) * DM;
    const __half* Kg = g_K + (size_t)b * SEQ * DM;
    const __half* Vg = g_V + (size_t)b * SEQ * DM;

    #pragma unroll
    for (int p = 0; p < 16; p++) {
        int q = p * 256 + t;
        int row = q >> 5, gr = q & 31;
        CP_ASYNC16(sb + AQ + row * ASTR + gr * 16,
                   (const char*)Qg + row * 512 + gr * 16);
    }
    #pragma unroll
    for (int p = 0; p < 8; p++) {
        int q = p * 256 + t;
        int row = q >> 5, gr = q & 31;
        CP_ASYNC16(sb + AK0 + row * ASTR + gr * 16,
                   (const char*)Kg + row * 512 + gr * 16);
        CP_ASYNC16(sb + AV0 + row * ASTR + gr * 16,
                   (const char*)Vg + row * 512 + gr * 16);
    }
    CP_COMMIT();

    const int wm = w & 3, wn = w >> 2;
    const int wm2 = w & 1, wn2 = w >> 1;

    const uint32_t qa_base = sb + AQ + (32 * wm + i8 + s1 * 8) * ASTR + s2 * 16;
    const uint32_t kb_lane = (uint32_t)(((q4 >> 1) * 8 + i8) * ASTR + (q4 & 1) * 16);
    const uint32_t vb_lane = (uint32_t)(((q4 & 1) * 8 + i8) * ASTR + (q4 >> 1) * 16);
    const uint32_t pa_base = sb + AP + (64 * wm2 + i8 + s1 * 8) * PSTR + s2 * 16;

    float oc[4][8][4] = {};
    float rsp[2][2] = {};
    const float scale = 0.0625f;

    for (int kt = 0; kt < NCHUNK; kt++) {
        CP_WAIT0();
        __syncthreads();
        const uint32_t kbuf = sb + (kt & 1 ? AK1 : AK0);
        const uint32_t vbuf = sb + (kt & 1 ? AV1 : AV0);

        // ---- S = Q K^T ----
        float sc[2][4][4] = {};
        #pragma unroll
        for (int kk = 0; kk < 16; kk++) {
            uint32_t a0[4], a1[4];
            ldsm4(a0, qa_base + kk * 32);
            ldsm4(a1, qa_base + 16 * ASTR + kk * 32);
            uint32_t bb[4];
            ldsm4(bb, kbuf + (uint32_t)(32 * wn) * ASTR + kb_lane + kk * 32);
            mma16816(sc[0][0], a0, bb[0], bb[1]);
            mma16816(sc[1][0], a1, bb[0], bb[1]);
            mma16816(sc[0][1], a0, bb[2], bb[3]);
            mma16816(sc[1][1], a1, bb[2], bb[3]);
            ldsm4(bb, kbuf + (uint32_t)(32 * wn + 16) * ASTR + kb_lane + kk * 32);
            mma16816(sc[0][2], a0, bb[0], bb[1]);
            mma16816(sc[1][2], a1, bb[0], bb[1]);
            mma16816(sc[0][3], a0, bb[2], bb[3]);
            mma16816(sc[1][3], a1, bb[2], bb[3]);
        }

        // ---- softmax ----
        #pragma unroll
        for (int mi = 0; mi < 2; mi++) {
            int rowA = 32 * wm + 16 * mi + g;
            char* pw = smem + AP + rowA * PSTR + (16 * wn + tg) * 4;
            #pragma unroll
            for (int nt = 0; nt < 4; nt++) {
                float p00 = __expf(sc[mi][nt][0] * scale);
                float p01 = __expf(sc[mi][nt][1] * scale);
                float p10 = __expf(sc[mi][nt][2] * scale);
                float p11 = __expf(sc[mi][nt][3] * scale);
                rsp[mi][0] += p00 + p01;
                rsp[mi][1] += p10 + p11;
                *(uint32_t*)(pw + nt * 16)            = pack_h2(p00, p01);
                *(uint32_t*)(pw + nt * 16 + 8 * PSTR) = pack_h2(p10, p11);
            }
        }
        __syncthreads();

        // ---- prefetch K/V(kt+1) ----
        if (kt + 1 < NCHUNK) {
            const __half* Kt = Kg + (size_t)(kt + 1) * TOK * DM;
            const __half* Vt = Vg + (size_t)(kt + 1) * TOK * DM;
            const uint32_t kdst = sb + ((kt + 1) & 1 ? AK1 : AK0);
            const uint32_t vdst = sb + ((kt + 1) & 1 ? AV1 : AV0);
            #pragma unroll
            for (int p = 0; p < 8; p++) {
                int q = p * 256 + t;
                int row = q >> 5, gr = q & 31;
                CP_ASYNC16(kdst + row * ASTR + gr * 16,
                           (const char*)Kt + row * 512 + gr * 16);
                CP_ASYNC16(vdst + row * ASTR + gr * 16,
                           (const char*)Vt + row * 512 + gr * 16);
            }
        }
        CP_COMMIT();

        // ---- O += P V ----
        #pragma unroll
        for (int kk2 = 0; kk2 < 4; kk2++) {
            uint32_t pa[4][4];
            #pragma unroll
            for (int mi = 0; mi < 4; mi++)
                ldsm4(pa[mi], pa_base + mi * 16 * PSTR + kk2 * 32);
            #pragma unroll
            for (int np = 0; np < 4; np++) {
                uint32_t bb[4];
                ldsm4t(bb, vbuf + (uint32_t)(kk2 * 16) * ASTR + vb_lane
                            + 128 * wn2 + np * 32);
                #pragma unroll
                for (int mi = 0; mi < 4; mi++) {
                    mma16816(oc[mi][2 * np],     pa[mi], bb[0], bb[1]);
                    mma16816(oc[mi][2 * np + 1], pa[mi], bb[2], bb[3]);
                }
            }
        }
    }

    // ---- rowsum finalize ----
    float* rs = (float*)(smem + ARS);
    #pragma unroll
    for (int mi = 0; mi < 2; mi++)
        #pragma unroll
        for (int h = 0; h < 2; h++) {
            float v = rsp[mi][h];
            v += __shfl_xor_sync(0xffffffffu, v, 1);
            v += __shfl_xor_sync(0xffffffffu, v, 2);
            if (tg == 0) rs[(32 * wm + 16 * mi + g + 8 * h) * 2 + wn] = v;
        }
    __syncthreads();

    // ---- output ----
    float* ob = out + ((size_t)b * SEQ + qt * 128) * DM;
    #pragma unroll
    for (int mi = 0; mi < 4; mi++) {
        int r0 = 64 * wm2 + 16 * mi + g;
        float inv0 = 1.0f / (rs[r0 * 2] + rs[r0 * 2 + 1]);
        float inv1 = 1.0f / (rs[(r0 + 8) * 2] + rs[(r0 + 8) * 2 + 1]);
        #pragma unroll
        for (int nt = 0; nt < 8; nt++) {
            int col = 64 * wn2 + 8 * nt + 2 * tg;
            *(float2*)(ob + (size_t)r0 * DM + col) =
                make_float2(oc[mi][nt][0] * inv0, oc[mi][nt][1] * inv0);
            *(float2*)(ob + (size_t)(r0 + 8) * DM + col) =
                make_float2(oc[mi][nt][2] * inv1, oc[mi][nt][3] * inv1);
        }
    }
}

extern "C" void kernel_launch(void* const* d_in, const int* in_sizes, int n_in,
                              void* d_out, int out_size)
{
    const float* x   = (const float*)d_in[0];
    const float* wq  = (const float*)d_in[1];
    const float* bq  = (const float*)d_in[2];
    const float* wk  = (const float*)d_in[3];
    const float* bk  = (const float*)d_in[4];
    const float* wv  = (const float*)d_in[5];
    const float* bv  = (const float*)d_in[6];
    const float* pos = (const float*)d_in[7];
    float* out = (float*)d_out;

    cudaFuncSetAttribute(qkv_v4, cudaFuncAttributeMaxDynamicSharedMemorySize,
                         QKV_SMEM);
    cudaFuncSetAttribute(attn_mma, cudaFuncAttributeMaxDynamicSharedMemorySize,
                         ATT_SMEM);

    wconv<<<192, 256>>>(wq, wk, wv);
    qkv_v4<<<dim3((NB * SEQ) / 128, 3), 256, QKV_SMEM>>>(x, pos, bq, bk, bv);
    attn_mma<<<dim3(SEQ / 128, NB), 256, ATT_SMEM>>>(out);
}

// round 15
// speedup vs baseline: 1.0596x; 1.0596x over previous
#include <cuda_runtime.h>
#include <cuda_fp16.h>
#include <math.h>
#include <stdint.h>

#define DM  256
#define SEQ 2304       // 48*48
#define NB  16

__device__ __half g_Q[NB * SEQ * DM];
__device__ __half g_K[NB * SEQ * DM];
__device__ __half g_V[NB * SEQ * DM];
__device__ __half g_W16[3 * DM * DM];

// ---------------------------------------------------------------------------
// helpers
// ---------------------------------------------------------------------------
__device__ __forceinline__ uint32_t smem_u32(const void* p) {
    uint32_t a;
    asm("{ .reg .u64 t; cvta.to.shared.u64 t, %1; cvt.u32.u64 %0, t; }"
        : "=r"(a) : "l"(p));
    return a;
}
__device__ __forceinline__ void ldsm4(uint32_t* r, uint32_t addr) {
    asm volatile("ldmatrix.sync.aligned.m8n8.x4.shared.b16 {%0,%1,%2,%3}, [%4];"
        : "=r"(r[0]), "=r"(r[1]), "=r"(r[2]), "=r"(r[3]) : "r"(addr));
}
__device__ __forceinline__ void ldsm4t(uint32_t* r, uint32_t addr) {
    asm volatile("ldmatrix.sync.aligned.m8n8.x4.trans.shared.b16 {%0,%1,%2,%3}, [%4];"
        : "=r"(r[0]), "=r"(r[1]), "=r"(r[2]), "=r"(r[3]) : "r"(addr));
}
__device__ __forceinline__ void mma16816(float* c, const uint32_t* a,
                                         uint32_t b0, uint32_t b1) {
    asm volatile(
        "mma.sync.aligned.m16n8k16.row.col.f32.f16.f16.f32 "
        "{%0,%1,%2,%3},{%4,%5,%6,%7},{%8,%9},{%0,%1,%2,%3};"
        : "+f"(c[0]), "+f"(c[1]), "+f"(c[2]), "+f"(c[3])
        : "r"(a[0]), "r"(a[1]), "r"(a[2]), "r"(a[3]), "r"(b0), "r"(b1));
}
__device__ __forceinline__ uint32_t pack_h2(float lo, float hi) {
    uint32_t r;
    asm("cvt.rn.f16x2.f32 %0, %1, %2;" : "=r"(r) : "f"(hi), "f"(lo));
    return r;
}
#define CP_ASYNC16(dst, src) \
    asm volatile("cp.async.cg.shared.global [%0], [%1], 16;" \
                 :: "r"(dst), "l"(src) : "memory")
#define CP_COMMIT() asm volatile("cp.async.commit_group;" ::: "memory")
#define CP_WAIT0()  asm volatile("cp.async.wait_group 0;" ::: "memory")
#define CP_WAIT1()  asm volatile("cp.async.wait_group 1;" ::: "memory")

#define ASTR 528                        // bytes per smem row (256h + 8h pad)

// ---------------------------------------------------------------------------
// W pre-convert (one-time). wq/bq get the 1/sqrt(d)=2^-4 scale folded in
// (exponent-exact in fp16 -> identical numerics, softmax skips the mul).
// ---------------------------------------------------------------------------
__global__ __launch_bounds__(256) void wconv(
    const float* __restrict__ wq, const float* __restrict__ wk,
    const float* __restrict__ wv)
{
    int i4 = (blockIdx.x * 256 + threadIdx.x) * 4;
    int wsel = i4 >> 16;
    int off  = i4 & 65535;
    const float* src = (wsel == 0) ? wq : (wsel == 1) ? wk : wv;
    float s = (wsel == 0) ? 0.0625f : 1.0f;
    float4 v = *(const float4*)(src + off);
    uint2 u;
    u.x = pack_h2(v.x * s, v.y * s);
    u.y = pack_h2(v.z * s, v.w * s);
    *(uint2*)(g_W16 + i4) = u;
}

// ---------------------------------------------------------------------------
// Fused QKV v3 (R9, verified ~55us). bq scaled by 2^-4 when staged.
// ---------------------------------------------------------------------------
#define QA  0
#define QW0 (128 * ASTR)
#define QW1 (QW0 + 128 * ASTR)
#define QBIA (QW1 + 128 * ASTR)
#define QKV_SMEM (QBIA + 3072)

__global__ __launch_bounds__(256, 1) void qkv_fused3(
    const float* __restrict__ x,  const float* __restrict__ pos,
    const float* __restrict__ bq, const float* __restrict__ bk,
    const float* __restrict__ bv)
{
    extern __shared__ char smem[];
    const uint32_t sb = smem_u32(smem);
    const int t = threadIdx.x, w = t >> 5, lane = t & 31;
    const int gq = lane >> 2, tg = lane & 3;
    const int i8 = lane & 7, s1 = (lane >> 3) & 1, s2 = (lane >> 4) & 1;
    const int q4 = lane >> 3;

    const int m0 = blockIdx.x * 128;
    const int sbase = m0 % SEQ;

    {
        const char* Wsrc = (const char*)g_W16;
        #pragma unroll
        for (int p = 0; p < 16; p++) {
            int q = p * 256 + t;
            int row = q >> 5, gr = q & 31;
            CP_ASYNC16(sb + QW0 + row * ASTR + gr * 16, Wsrc + row * 512 + gr * 16);
        }
        CP_COMMIT();
    }

    if (t < 192) {
        const float* src = (t < 64) ? bq : (t < 128) ? bk : bv;
        float s = (t < 64) ? 0.0625f : 1.0f;
        int off = (t & 63) * 4;
        float4 v = *(const float4*)(src + off);
        v.x *= s; v.y *= s; v.z *= s; v.w *= s;
        *(float4*)(smem + QBIA + (t >> 6) * 1024 + off * 4) = v;
    }

    #pragma unroll
    for (int p = 0; p < 32; p++) {
        int fid = p * 256 + t;
        int row = fid >> 6, c4 = fid & 63;
        float4 xa = *(const float4*)(x   + (size_t)(m0 + row) * DM + c4 * 4);
        float4 pa = *(const float4*)(pos + (size_t)(sbase + row) * DM + c4 * 4);
        uint2 u;
        u.x = pack_h2(xa.x + pa.x, xa.y + pa.y);
        u.y = pack_h2(xa.z + pa.z, xa.w + pa.w);
        *(uint2*)(smem + QA + row * ASTR + c4 * 8) = u;
    }

    const int wm2 = w & 1, wn2 = w >> 1;
    const uint32_t abase = sb + QA + (64 * wm2 + i8 + s1 * 8) * ASTR + s2 * 16;
    const uint32_t wb_lane = (uint32_t)(((q4 & 1) * 8 + i8) * ASTR + (q4 >> 1) * 16
                                        + 128 * wn2);

    __half* Os[3];
    Os[0] = g_Q; Os[1] = g_K; Os[2] = g_V;

    float acc[4][8][4] = {};

    #pragma unroll 1
    for (int c = 0; c < 6; c++) {
        const int wsel = c >> 1, kc = c & 1;
        const uint32_t wbuf = sb + ((c & 1) ? QW1 : QW0);

        if (c + 1 < 6) {
            const int nc = c + 1;
            const char* Wsrc = (const char*)(g_W16 + (nc >> 1) * 65536
                                             + (nc & 1) * 128 * DM);
            const uint32_t wdst = sb + ((nc & 1) ? QW1 : QW0);
            #pragma unroll
            for (int p = 0; p < 16; p++) {
                int q = p * 256 + t;
                int row = q >> 5, gr = q & 31;
                CP_ASYNC16(wdst + row * ASTR + gr * 16, Wsrc + row * 512 + gr * 16);
            }
            CP_COMMIT();
            CP_WAIT1();
        } else {
            CP_WAIT0();
        }
        __syncthreads();

        #pragma unroll
        for (int kk = 0; kk < 8; kk++) {
            uint32_t a[4][4];
            #pragma unroll
            for (int mi = 0; mi < 4; mi++)
                ldsm4(a[mi], abase + mi * 16 * ASTR + kc * 256 + kk * 32);
            #pragma unroll
            for (int np = 0; np < 4; np++) {
                uint32_t bb[4];
                ldsm4t(bb, wbuf + (uint32_t)(kk * 16) * ASTR + wb_lane + np * 32);
                #pragma unroll
                for (int mi = 0; mi < 4; mi++) {
                    mma16816(acc[mi][2 * np],     a[mi], bb[0], bb[1]);
                    mma16816(acc[mi][2 * np + 1], a[mi], bb[2], bb[3]);
                }
            }
        }

        if (kc == 1) {
            const float* bias = (const float*)(smem + QBIA + wsel * 1024);
            __half* outp = Os[wsel];
            #pragma unroll
            for (int mi = 0; mi < 4; mi++) {
                int r0 = 64 * wm2 + 16 * mi + gq;
                #pragma unroll
                for (int nt = 0; nt < 8; nt++) {
                    int col = 64 * wn2 + 8 * nt + 2 * tg;
                    float2 bv2 = *(const float2*)(bias + col);
                    *(uint32_t*)(outp + (size_t)(m0 + r0) * DM + col) =
                        pack_h2(acc[mi][nt][0] + bv2.x, acc[mi][nt][1] + bv2.y);
                    *(uint32_t*)(outp + (size_t)(m0 + r0 + 8) * DM + col) =
                        pack_h2(acc[mi][nt][2] + bv2.x, acc[mi][nt][3] + bv2.y);
                }
            }
            #pragma unroll
            for (int mi = 0; mi < 4; mi++)
                #pragma unroll
                for (int nt = 0; nt < 8; nt++)
                    #pragma unroll
                    for (int k2 = 0; k2 < 4; k2++)
                        acc[mi][nt][k2] = 0.0f;
        }
        __syncthreads();
    }
}

// ---------------------------------------------------------------------------
// Attention v9 (R8 tiling + fragment double-buffering + top prefetch):
// CTA = 128 q rows, 8 warps, TOK = 64.
// S-phase: 4 row-groups(32r) x 2 token-halves(32t); frags for kk+1 issued
//   before the 8 mma of kk (hides LDSM latency).
// O-phase: 2 row-groups(64r) x 4 d-slices(64d); V frags double-buffered.
// Q pre-scaled by 2^-4 (folded into wq) -> softmax is bare __expf.
// ---------------------------------------------------------------------------
#define TOK 64
#define NCHUNK (SEQ / TOK)       // 36
#define PSTR 144                 // P row stride (64h=128B + 16 pad)

#define AQ  0                        // Q  [128][528]   67584
#define AK0 (128 * ASTR)             // K buf0 [64][528]
#define AK1 (AK0 + 64 * ASTR)
#define AV0 (AK1 + 64 * ASTR)
#define AV1 (AV0 + 64 * ASTR)
#define AP  (AV1 + 64 * ASTR)        // P [128][144]
#define ARS (AP + 128 * PSTR)
#define ATT_SMEM (ARS + 1024)

__global__ __launch_bounds__(256, 1) void attn_mma(float* __restrict__ out)
{
    extern __shared__ char smem[];
    const uint32_t sb = smem_u32(smem);
    const int t = threadIdx.x, w = t >> 5, lane = t & 31;
    const int g = lane >> 2, tg = lane & 3;
    const int i8 = lane & 7, s1 = (lane >> 3) & 1, s2 = (lane >> 4) & 1;
    const int q4 = lane >> 3;

    const int qt = blockIdx.x, b = blockIdx.y;
    const __half* Qg = g_Q + ((size_t)b * SEQ + qt * 128) * DM;
    const __half* Kg = g_K + (size_t)b * SEQ * DM;
    const __half* Vg = g_V + (size_t)b * SEQ * DM;

    #pragma unroll
    for (int p = 0; p < 16; p++) {
        int q = p * 256 + t;
        int row = q >> 5, gr = q & 31;
        CP_ASYNC16(sb + AQ + row * ASTR + gr * 16,
                   (const char*)Qg + row * 512 + gr * 16);
    }
    #pragma unroll
    for (int p = 0; p < 8; p++) {
        int q = p * 256 + t;
        int row = q >> 5, gr = q & 31;
        CP_ASYNC16(sb + AK0 + row * ASTR + gr * 16,
                   (const char*)Kg + row * 512 + gr * 16);
        CP_ASYNC16(sb + AV0 + row * ASTR + gr * 16,
                   (const char*)Vg + row * 512 + gr * 16);
    }
    CP_COMMIT();

    const int wm = w & 3, wn = w >> 2;
    const int wm2 = w & 1, wn2 = w >> 1;

    const uint32_t qa_base = sb + AQ + (32 * wm + i8 + s1 * 8) * ASTR + s2 * 16;
    const uint32_t kb_lane = (uint32_t)(((q4 >> 1) * 8 + i8) * ASTR + (q4 & 1) * 16);
    const uint32_t vb_lane = (uint32_t)(((q4 & 1) * 8 + i8) * ASTR + (q4 >> 1) * 16);
    const uint32_t pa_base = sb + AP + (64 * wm2 + i8 + s1 * 8) * PSTR + s2 * 16;

    float oc[4][8][4] = {};
    float rsp[2][2] = {};

    for (int kt = 0; kt < NCHUNK; kt++) {
        CP_WAIT0();
        __syncthreads();   // K/V(kt) visible; prior-parity buffer reads done
        const uint32_t kbuf = sb + (kt & 1 ? AK1 : AK0);
        const uint32_t vbuf = sb + (kt & 1 ? AV1 : AV0);

        // ---- prefetch K/V(kt+1) at chunk top (full chunk to land) ----
        if (kt + 1 < NCHUNK) {
            const __half* Kt = Kg + (size_t)(kt + 1) * TOK * DM;
            const __half* Vt = Vg + (size_t)(kt + 1) * TOK * DM;
            const uint32_t kdst = sb + ((kt + 1) & 1 ? AK1 : AK0);
            const uint32_t vdst = sb + ((kt + 1) & 1 ? AV1 : AV0);
            #pragma unroll
            for (int p = 0; p < 8; p++) {
                int q = p * 256 + t;
                int row = q >> 5, gr = q & 31;
                CP_ASYNC16(kdst + row * ASTR + gr * 16,
                           (const char*)Kt + row * 512 + gr * 16);
                CP_ASYNC16(vdst + row * ASTR + gr * 16,
                           (const char*)Vt + row * 512 + gr * 16);
            }
        }
        CP_COMMIT();

        // ---- S = Q K^T (manually pipelined fragments) ----
        const uint32_t kbA = kbuf + (uint32_t)(32 * wn) * ASTR + kb_lane;
        const uint32_t kbB = kbuf + (uint32_t)(32 * wn + 16) * ASTR + kb_lane;
        float sc[2][4][4] = {};
        uint32_t a0[2][4], a1[2][4], f0[2][4], f1[2][4];
        ldsm4(a0[0], qa_base);
        ldsm4(a1[0], qa_base + 16 * ASTR);
        ldsm4(f0[0], kbA);
        ldsm4(f1[0], kbB);
        #pragma unroll
        for (int kk = 0; kk < 16; kk++) {
            const int cur = kk & 1, nxt = cur ^ 1;
            if (kk < 15) {
                ldsm4(a0[nxt], qa_base + (kk + 1) * 32);
                ldsm4(a1[nxt], qa_base + 16 * ASTR + (kk + 1) * 32);
                ldsm4(f0[nxt], kbA + (kk + 1) * 32);
                ldsm4(f1[nxt], kbB + (kk + 1) * 32);
            }
            mma16816(sc[0][0], a0[cur], f0[cur][0], f0[cur][1]);
            mma16816(sc[1][0], a1[cur], f0[cur][0], f0[cur][1]);
            mma16816(sc[0][1], a0[cur], f0[cur][2], f0[cur][3]);
            mma16816(sc[1][1], a1[cur], f0[cur][2], f0[cur][3]);
            mma16816(sc[0][2], a0[cur], f1[cur][0], f1[cur][1]);
            mma16816(sc[1][2], a1[cur], f1[cur][0], f1[cur][1]);
            mma16816(sc[0][3], a0[cur], f1[cur][2], f1[cur][3]);
            mma16816(sc[1][3], a1[cur], f1[cur][2], f1[cur][3]);
        }

        // ---- softmax (Q pre-scaled; bare exp) ----
        #pragma unroll
        for (int mi = 0; mi < 2; mi++) {
            int rowA = 32 * wm + 16 * mi + g;
            char* pw = smem + AP + rowA * PSTR + (16 * wn + tg) * 4;
            #pragma unroll
            for (int nt = 0; nt < 4; nt++) {
                float p00 = __expf(sc[mi][nt][0]);
                float p01 = __expf(sc[mi][nt][1]);
                float p10 = __expf(sc[mi][nt][2]);
                float p11 = __expf(sc[mi][nt][3]);
                rsp[mi][0] += p00 + p01;
                rsp[mi][1] += p10 + p11;
                *(uint32_t*)(pw + nt * 16)            = pack_h2(p00, p01);
                *(uint32_t*)(pw + nt * 16 + 8 * PSTR) = pack_h2(p10, p11);
            }
        }
        __syncthreads();

        // ---- O += P V (V frags double-buffered) ----
        #pragma unroll
        for (int kk2 = 0; kk2 < 4; kk2++) {
            const uint32_t vrow = vbuf + (uint32_t)(kk2 * 16) * ASTR + vb_lane
                                  + 128 * wn2;
            uint32_t pa[4][4];
            #pragma unroll
            for (int mi = 0; mi < 4; mi++)
                ldsm4(pa[mi], pa_base + mi * 16 * PSTR + kk2 * 32);
            uint32_t vb[2][4];
            ldsm4t(vb[0], vrow);
            #pragma unroll
            for (int np = 0; np < 4; np++) {
                const int cur = np & 1, nxt = cur ^ 1;
                if (np < 3) ldsm4t(vb[nxt], vrow + (np + 1) * 32);
                #pragma unroll
                for (int mi = 0; mi < 4; mi++) {
                    mma16816(oc[mi][2 * np],     pa[mi], vb[cur][0], vb[cur][1]);
                    mma16816(oc[mi][2 * np + 1], pa[mi], vb[cur][2], vb[cur][3]);
                }
            }
        }
    }

    // ---- rowsum finalize ----
    float* rs = (float*)(smem + ARS);
    #pragma unroll
    for (int mi = 0; mi < 2; mi++)
        #pragma unroll
        for (int h = 0; h < 2; h++) {
            float v = rsp[mi][h];
            v += __shfl_xor_sync(0xffffffffu, v, 1);
            v += __shfl_xor_sync(0xffffffffu, v, 2);
            if (tg == 0) rs[(32 * wm + 16 * mi + g + 8 * h) * 2 + wn] = v;
        }
    __syncthreads();

    // ---- output ----
    float* ob = out + ((size_t)b * SEQ + qt * 128) * DM;
    #pragma unroll
    for (int mi = 0; mi < 4; mi++) {
        int r0 = 64 * wm2 + 16 * mi + g;
        float inv0 = 1.0f / (rs[r0 * 2] + rs[r0 * 2 + 1]);
        float inv1 = 1.0f / (rs[(r0 + 8) * 2] + rs[(r0 + 8) * 2 + 1]);
        #pragma unroll
        for (int nt = 0; nt < 8; nt++) {
            int col = 64 * wn2 + 8 * nt + 2 * tg;
            *(float2*)(ob + (size_t)r0 * DM + col) =
                make_float2(oc[mi][nt][0] * inv0, oc[mi][nt][1] * inv0);
            *(float2*)(ob + (size_t)(r0 + 8) * DM + col) =
                make_float2(oc[mi][nt][2] * inv1, oc[mi][nt][3] * inv1);
        }
    }
}

extern "C" void kernel_launch(void* const* d_in, const int* in_sizes, int n_in,
                              void* d_out, int out_size)
{
    const float* x   = (const float*)d_in[0];
    const float* wq  = (const float*)d_in[1];
    const float* bq  = (const float*)d_in[2];
    const float* wk  = (const float*)d_in[3];
    const float* bk  = (const float*)d_in[4];
    const float* wv  = (const float*)d_in[5];
    const float* bv  = (const float*)d_in[6];
    const float* pos = (const float*)d_in[7];
    float* out = (float*)d_out;

    cudaFuncSetAttribute(qkv_fused3, cudaFuncAttributeMaxDynamicSharedMemorySize,
                         QKV_SMEM);
    cudaFuncSetAttribute(attn_mma, cudaFuncAttributeMaxDynamicSharedMemorySize,
                         ATT_SMEM);

    wconv<<<192, 256>>>(wq, wk, wv);
    qkv_fused3<<<(NB * SEQ) / 128, 256, QKV_SMEM>>>(x, pos, bq, bk, bv);
    attn_mma<<<dim3(SEQ / 128, NB), 256, ATT_SMEM>>>(out);
}

// round 16
// speedup vs baseline: 1.0630x; 1.0033x over previous
#include <cuda_runtime.h>
#include <cuda_fp16.h>
#include <math.h>
#include <stdint.h>

#define DM  256
#define SEQ 2304       // 48*48
#define NB  16

__device__ __half g_Q[NB * SEQ * DM];
__device__ __half g_K[NB * SEQ * DM];
__device__ __half g_V[NB * SEQ * DM];
__device__ __half g_W16[3 * DM * DM];
__device__ __half g_XH[NB * SEQ * DM];    // fp16(x + pos)

// ---------------------------------------------------------------------------
// helpers
// ---------------------------------------------------------------------------
__device__ __forceinline__ uint32_t smem_u32(const void* p) {
    uint32_t a;
    asm("{ .reg .u64 t; cvta.to.shared.u64 t, %1; cvt.u32.u64 %0, t; }"
        : "=r"(a) : "l"(p));
    return a;
}
__device__ __forceinline__ void ldsm4(uint32_t* r, uint32_t addr) {
    asm volatile("ldmatrix.sync.aligned.m8n8.x4.shared.b16 {%0,%1,%2,%3}, [%4];"
        : "=r"(r[0]), "=r"(r[1]), "=r"(r[2]), "=r"(r[3]) : "r"(addr));
}
__device__ __forceinline__ void ldsm4t(uint32_t* r, uint32_t addr) {
    asm volatile("ldmatrix.sync.aligned.m8n8.x4.trans.shared.b16 {%0,%1,%2,%3}, [%4];"
        : "=r"(r[0]), "=r"(r[1]), "=r"(r[2]), "=r"(r[3]) : "r"(addr));
}
__device__ __forceinline__ void mma16816(float* c, const uint32_t* a,
                                         uint32_t b0, uint32_t b1) {
    asm volatile(
        "mma.sync.aligned.m16n8k16.row.col.f32.f16.f16.f32 "
        "{%0,%1,%2,%3},{%4,%5,%6,%7},{%8,%9},{%0,%1,%2,%3};"
        : "+f"(c[0]), "+f"(c[1]), "+f"(c[2]), "+f"(c[3])
        : "r"(a[0]), "r"(a[1]), "r"(a[2]), "r"(a[3]), "r"(b0), "r"(b1));
}
__device__ __forceinline__ uint32_t pack_h2(float lo, float hi) {
    uint32_t r;
    asm("cvt.rn.f16x2.f32 %0, %1, %2;" : "=r"(r) : "f"(hi), "f"(lo));
    return r;
}
#define CP_ASYNC16(dst, src) \
    asm volatile("cp.async.cg.shared.global [%0], [%1], 16;" \
                 :: "r"(dst), "l"(src) : "memory")
#define CP_COMMIT() asm volatile("cp.async.commit_group;" ::: "memory")
#define CP_WAIT0()  asm volatile("cp.async.wait_group 0;" ::: "memory")
#define CP_WAIT1()  asm volatile("cp.async.wait_group 1;" ::: "memory")

#define ASTR 528                        // bytes per smem row (256h + 8h pad)

// ---------------------------------------------------------------------------
// prep: (a) xh = fp16(x + pos)  — 9216 blocks
//       (b) W fp32 -> fp16 (wq scaled by 2^-4) — 192 blocks
// ---------------------------------------------------------------------------
#define XH_BLOCKS 9216
__global__ __launch_bounds__(256) void prep(
    const float* __restrict__ x,  const float* __restrict__ pos,
    const float* __restrict__ wq, const float* __restrict__ wk,
    const float* __restrict__ wv)
{
    if (blockIdx.x < XH_BLOCKS) {
        int i4 = (blockIdx.x * 256 + threadIdx.x) * 4;
        int row  = i4 >> 8;
        int srow = row % SEQ;
        int col  = i4 & 255;
        float4 xa = *(const float4*)(x + i4);
        float4 pa = *(const float4*)(pos + srow * DM + col);
        uint2 u;
        u.x = pack_h2(xa.x + pa.x, xa.y + pa.y);
        u.y = pack_h2(xa.z + pa.z, xa.w + pa.w);
        *(uint2*)(g_XH + i4) = u;
    } else {
        int j  = (blockIdx.x - XH_BLOCKS) * 256 + threadIdx.x;
        int i4 = j * 4;
        int wsel = i4 >> 16;
        int off  = i4 & 65535;
        const float* src = (wsel == 0) ? wq : (wsel == 1) ? wk : wv;
        float s = (wsel == 0) ? 0.0625f : 1.0f;
        float4 v = *(const float4*)(src + off);
        uint2 u;
        u.x = pack_h2(v.x * s, v.y * s);
        u.y = pack_h2(v.z * s, v.w * s);
        *(uint2*)(g_W16 + i4) = u;
    }
}

// ---------------------------------------------------------------------------
// Fused QKV v5: A (fp16 xh) via cp.async + W streamed fp16, all async.
// Group structure: [A + W0] [W1] [W2] ... ; per-chunk wait_group 1.
// ---------------------------------------------------------------------------
#define QA  0
#define QW0 (128 * ASTR)
#define QW1 (QW0 + 128 * ASTR)
#define QBIA (QW1 + 128 * ASTR)
#define QKV_SMEM (QBIA + 3072)

__global__ __launch_bounds__(256, 1) void qkv_fused5(
    const float* __restrict__ bq, const float* __restrict__ bk,
    const float* __restrict__ bv)
{
    extern __shared__ char smem[];
    const uint32_t sb = smem_u32(smem);
    const int t = threadIdx.x, w = t >> 5, lane = t & 31;
    const int gq = lane >> 2, tg = lane & 3;
    const int i8 = lane & 7, s1 = (lane >> 3) & 1, s2 = (lane >> 4) & 1;
    const int q4 = lane >> 3;

    const int m0 = blockIdx.x * 128;

    // ---- group 1: A tile (64 KB fp16) + W chunk 0 (128 k-rows) ----
    {
        const char* Ax = (const char*)(g_XH + (size_t)m0 * DM);
        #pragma unroll
        for (int p = 0; p < 16; p++) {
            int q = p * 256 + t;
            int row = q >> 5, gr = q & 31;
            CP_ASYNC16(sb + QA + row * ASTR + gr * 16, Ax + row * 512 + gr * 16);
        }
        const char* Wsrc = (const char*)g_W16;
        #pragma unroll
        for (int p = 0; p < 16; p++) {
            int q = p * 256 + t;
            int row = q >> 5, gr = q & 31;
            CP_ASYNC16(sb + QW0 + row * ASTR + gr * 16, Wsrc + row * 512 + gr * 16);
        }
        CP_COMMIT();
    }

    // bias -> smem (bq scaled by 2^-4)
    if (t < 192) {
        const float* src = (t < 64) ? bq : (t < 128) ? bk : bv;
        float s = (t < 64) ? 0.0625f : 1.0f;
        int off = (t & 63) * 4;
        float4 v = *(const float4*)(src + off);
        v.x *= s; v.y *= s; v.z *= s; v.w *= s;
        *(float4*)(smem + QBIA + (t >> 6) * 1024 + off * 4) = v;
    }

    const int wm2 = w & 1, wn2 = w >> 1;
    const uint32_t abase = sb + QA + (64 * wm2 + i8 + s1 * 8) * ASTR + s2 * 16;
    const uint32_t wb_lane = (uint32_t)(((q4 & 1) * 8 + i8) * ASTR + (q4 >> 1) * 16
                                        + 128 * wn2);

    __half* Os[3];
    Os[0] = g_Q; Os[1] = g_K; Os[2] = g_V;

    float acc[4][8][4] = {};

    #pragma unroll 1
    for (int c = 0; c < 6; c++) {
        const int wsel = c >> 1, kc = c & 1;
        const uint32_t wbuf = sb + ((c & 1) ? QW1 : QW0);

        if (c + 1 < 6) {
            const int nc = c + 1;
            const char* Wsrc = (const char*)(g_W16 + (nc >> 1) * 65536
                                             + (nc & 1) * 128 * DM);
            const uint32_t wdst = sb + ((nc & 1) ? QW1 : QW0);
            #pragma unroll
            for (int p = 0; p < 16; p++) {
                int q = p * 256 + t;
                int row = q >> 5, gr = q & 31;
                CP_ASYNC16(wdst + row * ASTR + gr * 16, Wsrc + row * 512 + gr * 16);
            }
            CP_COMMIT();
            CP_WAIT1();     // A + W(c) done; W(c+1) in flight
        } else {
            CP_WAIT0();
        }
        __syncthreads();

        #pragma unroll
        for (int kk = 0; kk < 8; kk++) {
            uint32_t a[4][4];
            #pragma unroll
            for (int mi = 0; mi < 4; mi++)
                ldsm4(a[mi], abase + mi * 16 * ASTR + kc * 256 + kk * 32);
            #pragma unroll
            for (int np = 0; np < 4; np++) {
                uint32_t bb[4];
                ldsm4t(bb, wbuf + (uint32_t)(kk * 16) * ASTR + wb_lane + np * 32);
                #pragma unroll
                for (int mi = 0; mi < 4; mi++) {
                    mma16816(acc[mi][2 * np],     a[mi], bb[0], bb[1]);
                    mma16816(acc[mi][2 * np + 1], a[mi], bb[2], bb[3]);
                }
            }
        }

        if (kc == 1) {
            const float* bias = (const float*)(smem + QBIA + wsel * 1024);
            __half* outp = Os[wsel];
            #pragma unroll
            for (int mi = 0; mi < 4; mi++) {
                int r0 = 64 * wm2 + 16 * mi + gq;
                #pragma unroll
                for (int nt = 0; nt < 8; nt++) {
                    int col = 64 * wn2 + 8 * nt + 2 * tg;
                    float2 bv2 = *(const float2*)(bias + col);
                    *(uint32_t*)(outp + (size_t)(m0 + r0) * DM + col) =
                        pack_h2(acc[mi][nt][0] + bv2.x, acc[mi][nt][1] + bv2.y);
                    *(uint32_t*)(outp + (size_t)(m0 + r0 + 8) * DM + col) =
                        pack_h2(acc[mi][nt][2] + bv2.x, acc[mi][nt][3] + bv2.y);
                }
            }
            #pragma unroll
            for (int mi = 0; mi < 4; mi++)
                #pragma unroll
                for (int nt = 0; nt < 8; nt++)
                    #pragma unroll
                    for (int k2 = 0; k2 < 4; k2++)
                        acc[mi][nt][k2] = 0.0f;
        }
        __syncthreads();
    }
}

// ---------------------------------------------------------------------------
// Attention (R15, best verified): CTA = 128 q rows, 8 warps, TOK = 64.
// S-phase: 4 row-groups(32r) x 2 token-halves(32t); fragments double-buffered.
// P (128x64 fp16) roundtrips through smem.
// O-phase: 2 row-groups(64r) x 4 d-slices(64d); V frags double-buffered.
// Q pre-scaled by 2^-4 -> bare __expf.
// ---------------------------------------------------------------------------
#define TOK 64
#define NCHUNK (SEQ / TOK)       // 36
#define PSTR 144                 // P row stride (64h=128B + 16 pad)

#define AQ  0                        // Q  [128][528]   67584
#define AK0 (128 * ASTR)             // K buf0 [64][528]
#define AK1 (AK0 + 64 * ASTR)
#define AV0 (AK1 + 64 * ASTR)
#define AV1 (AV0 + 64 * ASTR)
#define AP  (AV1 + 64 * ASTR)        // P [128][144]
#define ARS (AP + 128 * PSTR)
#define ATT_SMEM (ARS + 1024)

__global__ __launch_bounds__(256, 1) void attn_mma(float* __restrict__ out)
{
    extern __shared__ char smem[];
    const uint32_t sb = smem_u32(smem);
    const int t = threadIdx.x, w = t >> 5, lane = t & 31;
    const int g = lane >> 2, tg = lane & 3;
    const int i8 = lane & 7, s1 = (lane >> 3) & 1, s2 = (lane >> 4) & 1;
    const int q4 = lane >> 3;

    const int qt = blockIdx.x, b = blockIdx.y;
    const __half* Qg = g_Q + ((size_t)b * SEQ + qt * 128) * DM;
    const __half* Kg = g_K + (size_t)b * SEQ * DM;
    const __half* Vg = g_V + (size_t)b * SEQ * DM;

    #pragma unroll
    for (int p = 0; p < 16; p++) {
        int q = p * 256 + t;
        int row = q >> 5, gr = q & 31;
        CP_ASYNC16(sb + AQ + row * ASTR + gr * 16,
                   (const char*)Qg + row * 512 + gr * 16);
    }
    #pragma unroll
    for (int p = 0; p < 8; p++) {
        int q = p * 256 + t;
        int row = q >> 5, gr = q & 31;
        CP_ASYNC16(sb + AK0 + row * ASTR + gr * 16,
                   (const char*)Kg + row * 512 + gr * 16);
        CP_ASYNC16(sb + AV0 + row * ASTR + gr * 16,
                   (const char*)Vg + row * 512 + gr * 16);
    }
    CP_COMMIT();

    const int wm = w & 3, wn = w >> 2;
    const int wm2 = w & 1, wn2 = w >> 1;

    const uint32_t qa_base = sb + AQ + (32 * wm + i8 + s1 * 8) * ASTR + s2 * 16;
    const uint32_t kb_lane = (uint32_t)(((q4 >> 1) * 8 + i8) * ASTR + (q4 & 1) * 16);
    const uint32_t vb_lane = (uint32_t)(((q4 & 1) * 8 + i8) * ASTR + (q4 >> 1) * 16);
    const uint32_t pa_base = sb + AP + (64 * wm2 + i8 + s1 * 8) * PSTR + s2 * 16;

    float oc[4][8][4] = {};
    float rsp[2][2] = {};

    for (int kt = 0; kt < NCHUNK; kt++) {
        CP_WAIT0();
        __syncthreads();
        const uint32_t kbuf = sb + (kt & 1 ? AK1 : AK0);
        const uint32_t vbuf = sb + (kt & 1 ? AV1 : AV0);

        if (kt + 1 < NCHUNK) {
            const __half* Kt = Kg + (size_t)(kt + 1) * TOK * DM;
            const __half* Vt = Vg + (size_t)(kt + 1) * TOK * DM;
            const uint32_t kdst = sb + ((kt + 1) & 1 ? AK1 : AK0);
            const uint32_t vdst = sb + ((kt + 1) & 1 ? AV1 : AV0);
            #pragma unroll
            for (int p = 0; p < 8; p++) {
                int q = p * 256 + t;
                int row = q >> 5, gr = q & 31;
                CP_ASYNC16(kdst + row * ASTR + gr * 16,
                           (const char*)Kt + row * 512 + gr * 16);
                CP_ASYNC16(vdst + row * ASTR + gr * 16,
                           (const char*)Vt + row * 512 + gr * 16);
            }
        }
        CP_COMMIT();

        // ---- S = Q K^T (pipelined fragments) ----
        const uint32_t kbA = kbuf + (uint32_t)(32 * wn) * ASTR + kb_lane;
        const uint32_t kbB = kbuf + (uint32_t)(32 * wn + 16) * ASTR + kb_lane;
        float sc[2][4][4] = {};
        uint32_t a0[2][4], a1[2][4], f0[2][4], f1[2][4];
        ldsm4(a0[0], qa_base);
        ldsm4(a1[0], qa_base + 16 * ASTR);
        ldsm4(f0[0], kbA);
        ldsm4(f1[0], kbB);
        #pragma unroll
        for (int kk = 0; kk < 16; kk++) {
            const int cur = kk & 1, nxt = cur ^ 1;
            if (kk < 15) {
                ldsm4(a0[nxt], qa_base + (kk + 1) * 32);
                ldsm4(a1[nxt], qa_base + 16 * ASTR + (kk + 1) * 32);
                ldsm4(f0[nxt], kbA + (kk + 1) * 32);
                ldsm4(f1[nxt], kbB + (kk + 1) * 32);
            }
            mma16816(sc[0][0], a0[cur], f0[cur][0], f0[cur][1]);
            mma16816(sc[1][0], a1[cur], f0[cur][0], f0[cur][1]);
            mma16816(sc[0][1], a0[cur], f0[cur][2], f0[cur][3]);
            mma16816(sc[1][1], a1[cur], f0[cur][2], f0[cur][3]);
            mma16816(sc[0][2], a0[cur], f1[cur][0], f1[cur][1]);
            mma16816(sc[1][2], a1[cur], f1[cur][0], f1[cur][1]);
            mma16816(sc[0][3], a0[cur], f1[cur][2], f1[cur][3]);
            mma16816(sc[1][3], a1[cur], f1[cur][2], f1[cur][3]);
        }

        // ---- softmax (bare exp) ----
        #pragma unroll
        for (int mi = 0; mi < 2; mi++) {
            int rowA = 32 * wm + 16 * mi + g;
            char* pw = smem + AP + rowA * PSTR + (16 * wn + tg) * 4;
            #pragma unroll
            for (int nt = 0; nt < 4; nt++) {
                float p00 = __expf(sc[mi][nt][0]);
                float p01 = __expf(sc[mi][nt][1]);
                float p10 = __expf(sc[mi][nt][2]);
                float p11 = __expf(sc[mi][nt][3]);
                rsp[mi][0] += p00 + p01;
                rsp[mi][1] += p10 + p11;
                *(uint32_t*)(pw + nt * 16)            = pack_h2(p00, p01);
                *(uint32_t*)(pw + nt * 16 + 8 * PSTR) = pack_h2(p10, p11);
            }
        }
        __syncthreads();

        // ---- O += P V (V frags double-buffered) ----
        #pragma unroll
        for (int kk2 = 0; kk2 < 4; kk2++) {
            const uint32_t vrow = vbuf + (uint32_t)(kk2 * 16) * ASTR + vb_lane
                                  + 128 * wn2;
            uint32_t pa[4][4];
            #pragma unroll
            for (int mi = 0; mi < 4; mi++)
                ldsm4(pa[mi], pa_base + mi * 16 * PSTR + kk2 * 32);
            uint32_t vb[2][4];
            ldsm4t(vb[0], vrow);
            #pragma unroll
            for (int np = 0; np < 4; np++) {
                const int cur = np & 1, nxt = cur ^ 1;
                if (np < 3) ldsm4t(vb[nxt], vrow + (np + 1) * 32);
                #pragma unroll
                for (int mi = 0; mi < 4; mi++) {
                    mma16816(oc[mi][2 * np],     pa[mi], vb[cur][0], vb[cur][1]);
                    mma16816(oc[mi][2 * np + 1], pa[mi], vb[cur][2], vb[cur][3]);
                }
            }
        }
    }

    // ---- rowsum finalize ----
    float* rs = (float*)(smem + ARS);
    #pragma unroll
    for (int mi = 0; mi < 2; mi++)
        #pragma unroll
        for (int h = 0; h < 2; h++) {
            float v = rsp[mi][h];
            v += __shfl_xor_sync(0xffffffffu, v, 1);
            v += __shfl_xor_sync(0xffffffffu, v, 2);
            if (tg == 0) rs[(32 * wm + 16 * mi + g + 8 * h) * 2 + wn] = v;
        }
    __syncthreads();

    // ---- output ----
    float* ob = out + ((size_t)b * SEQ + qt * 128) * DM;
    #pragma unroll
    for (int mi = 0; mi < 4; mi++) {
        int r0 = 64 * wm2 + 16 * mi + g;
        float inv0 = 1.0f / (rs[r0 * 2] + rs[r0 * 2 + 1]);
        float inv1 = 1.0f / (rs[(r0 + 8) * 2] + rs[(r0 + 8) * 2 + 1]);
        #pragma unroll
        for (int nt = 0; nt < 8; nt++) {
            int col = 64 * wn2 + 8 * nt + 2 * tg;
            *(float2*)(ob + (size_t)r0 * DM + col) =
                make_float2(oc[mi][nt][0] * inv0, oc[mi][nt][1] * inv0);
            *(float2*)(ob + (size_t)(r0 + 8) * DM + col) =
                make_float2(oc[mi][nt][2] * inv1, oc[mi][nt][3] * inv1);
        }
    }
}

extern "C" void kernel_launch(void* const* d_in, const int* in_sizes, int n_in,
                              void* d_out, int out_size)
{
    const float* x   = (const float*)d_in[0];
    const float* wq  = (const float*)d_in[1];
    const float* bq  = (const float*)d_in[2];
    const float* wk  = (const float*)d_in[3];
    const float* bk  = (const float*)d_in[4];
    const float* wv  = (const float*)d_in[5];
    const float* bv  = (const float*)d_in[6];
    const float* pos = (const float*)d_in[7];
    float* out = (float*)d_out;

    cudaFuncSetAttribute(qkv_fused5, cudaFuncAttributeMaxDynamicSharedMemorySize,
                         QKV_SMEM);
    cudaFuncSetAttribute(attn_mma, cudaFuncAttributeMaxDynamicSharedMemorySize,
                         ATT_SMEM);

    prep<<<XH_BLOCKS + 192, 256>>>(x, pos, wq, wk, wv);
    qkv_fused5<<<(NB * SEQ) / 128, 256, QKV_SMEM>>>(bq, bk, bv);
    attn_mma<<<dim3(SEQ / 128, NB), 256, ATT_SMEM>>>(out);
}

// round 17
// speedup vs baseline: 1.0683x; 1.0050x over previous
#include <cuda_runtime.h>
#include <cuda_fp16.h>
#include <math.h>
#include <stdint.h>

#define DM  256
#define SEQ 2304       // 48*48
#define NB  16

__device__ __half g_Q[NB * SEQ * DM];
__device__ __half g_K[NB * SEQ * DM];
__device__ __half g_V[NB * SEQ * DM];
__device__ __half g_W16[3 * DM * DM];
__device__ __half g_XH[NB * SEQ * DM];    // fp16(x + pos)

// ---------------------------------------------------------------------------
// helpers
// ---------------------------------------------------------------------------
__device__ __forceinline__ uint32_t smem_u32(const void* p) {
    uint32_t a;
    asm("{ .reg .u64 t; cvta.to.shared.u64 t, %1; cvt.u32.u64 %0, t; }"
        : "=r"(a) : "l"(p));
    return a;
}
__device__ __forceinline__ void ldsm4(uint32_t* r, uint32_t addr) {
    asm volatile("ldmatrix.sync.aligned.m8n8.x4.shared.b16 {%0,%1,%2,%3}, [%4];"
        : "=r"(r[0]), "=r"(r[1]), "=r"(r[2]), "=r"(r[3]) : "r"(addr));
}
__device__ __forceinline__ void ldsm4t(uint32_t* r, uint32_t addr) {
    asm volatile("ldmatrix.sync.aligned.m8n8.x4.trans.shared.b16 {%0,%1,%2,%3}, [%4];"
        : "=r"(r[0]), "=r"(r[1]), "=r"(r[2]), "=r"(r[3]) : "r"(addr));
}
__device__ __forceinline__ void mma16816(float* c, const uint32_t* a,
                                         uint32_t b0, uint32_t b1) {
    asm volatile(
        "mma.sync.aligned.m16n8k16.row.col.f32.f16.f16.f32 "
        "{%0,%1,%2,%3},{%4,%5,%6,%7},{%8,%9},{%0,%1,%2,%3};"
        : "+f"(c[0]), "+f"(c[1]), "+f"(c[2]), "+f"(c[3])
        : "r"(a[0]), "r"(a[1]), "r"(a[2]), "r"(a[3]), "r"(b0), "r"(b1));
}
__device__ __forceinline__ uint32_t pack_h2(float lo, float hi) {
    uint32_t r;
    asm("cvt.rn.f16x2.f32 %0, %1, %2;" : "=r"(r) : "f"(hi), "f"(lo));
    return r;
}
#define CP_ASYNC16(dst, src) \
    asm volatile("cp.async.cg.shared.global [%0], [%1], 16;" \
                 :: "r"(dst), "l"(src) : "memory")
#define CP_COMMIT() asm volatile("cp.async.commit_group;" ::: "memory")
#define CP_WAIT0()  asm volatile("cp.async.wait_group 0;" ::: "memory")
#define CP_WAIT1()  asm volatile("cp.async.wait_group 1;" ::: "memory")

#define ASTR 528                        // bytes per smem row (256h + 8h pad)

// ---------------------------------------------------------------------------
// prep v2 (grid-strided): xh = fp16(x+pos) in 2304 blocks x 4 float4/thread;
// W fp32->fp16 (wq scaled 2^-4) in 48 blocks x 4 float4/thread.
// ---------------------------------------------------------------------------
#define XH_BLOCKS2 2304
__global__ __launch_bounds__(256) void prep(
    const float* __restrict__ x,  const float* __restrict__ pos,
    const float* __restrict__ wq, const float* __restrict__ wk,
    const float* __restrict__ wv)
{
    const int t = threadIdx.x;
    if (blockIdx.x < XH_BLOCKS2) {
        #pragma unroll
        for (int p = 0; p < 4; p++) {
            int i4 = ((blockIdx.x * 4 + p) * 256 + t) * 4;
            int row  = i4 >> 8;
            int srow = row % SEQ;
            int col  = i4 & 255;
            float4 xa = *(const float4*)(x + i4);
            float4 pa = *(const float4*)(pos + srow * DM + col);
            uint2 u;
            u.x = pack_h2(xa.x + pa.x, xa.y + pa.y);
            u.y = pack_h2(xa.z + pa.z, xa.w + pa.w);
            *(uint2*)(g_XH + i4) = u;
        }
    } else {
        const int bb = blockIdx.x - XH_BLOCKS2;
        #pragma unroll
        for (int p = 0; p < 4; p++) {
            int i4 = ((bb * 4 + p) * 256 + t) * 4;
            int wsel = i4 >> 16;
            int off  = i4 & 65535;
            const float* src = (wsel == 0) ? wq : (wsel == 1) ? wk : wv;
            float s = (wsel == 0) ? 0.0625f : 1.0f;
            float4 v = *(const float4*)(src + off);
            uint2 u;
            u.x = pack_h2(v.x * s, v.y * s);
            u.y = pack_h2(v.z * s, v.w * s);
            *(uint2*)(g_W16 + i4) = u;
        }
    }
}

// ---------------------------------------------------------------------------
// Fused QKV v5 (R16, verified): A (fp16 xh) via cp.async + W streamed fp16.
// Group structure: [A + W0] [W1] [W2] ... ; per-chunk wait_group 1.
// ---------------------------------------------------------------------------
#define QA  0
#define QW0 (128 * ASTR)
#define QW1 (QW0 + 128 * ASTR)
#define QBIA (QW1 + 128 * ASTR)
#define QKV_SMEM (QBIA + 3072)

__global__ __launch_bounds__(256, 1) void qkv_fused5(
    const float* __restrict__ bq, const float* __restrict__ bk,
    const float* __restrict__ bv)
{
    extern __shared__ char smem[];
    const uint32_t sb = smem_u32(smem);
    const int t = threadIdx.x, w = t >> 5, lane = t & 31;
    const int gq = lane >> 2, tg = lane & 3;
    const int i8 = lane & 7, s1 = (lane >> 3) & 1, s2 = (lane >> 4) & 1;
    const int q4 = lane >> 3;

    const int m0 = blockIdx.x * 128;

    // ---- group 1: A tile (64 KB fp16) + W chunk 0 (128 k-rows) ----
    {
        const char* Ax = (const char*)(g_XH + (size_t)m0 * DM);
        #pragma unroll
        for (int p = 0; p < 16; p++) {
            int q = p * 256 + t;
            int row = q >> 5, gr = q & 31;
            CP_ASYNC16(sb + QA + row * ASTR + gr * 16, Ax + row * 512 + gr * 16);
        }
        const char* Wsrc = (const char*)g_W16;
        #pragma unroll
        for (int p = 0; p < 16; p++) {
            int q = p * 256 + t;
            int row = q >> 5, gr = q & 31;
            CP_ASYNC16(sb + QW0 + row * ASTR + gr * 16, Wsrc + row * 512 + gr * 16);
        }
        CP_COMMIT();
    }

    // bias -> smem (bq scaled by 2^-4)
    if (t < 192) {
        const float* src = (t < 64) ? bq : (t < 128) ? bk : bv;
        float s = (t < 64) ? 0.0625f : 1.0f;
        int off = (t & 63) * 4;
        float4 v = *(const float4*)(src + off);
        v.x *= s; v.y *= s; v.z *= s; v.w *= s;
        *(float4*)(smem + QBIA + (t >> 6) * 1024 + off * 4) = v;
    }

    const int wm2 = w & 1, wn2 = w >> 1;
    const uint32_t abase = sb + QA + (64 * wm2 + i8 + s1 * 8) * ASTR + s2 * 16;
    const uint32_t wb_lane = (uint32_t)(((q4 & 1) * 8 + i8) * ASTR + (q4 >> 1) * 16
                                        + 128 * wn2);

    __half* Os[3];
    Os[0] = g_Q; Os[1] = g_K; Os[2] = g_V;

    float acc[4][8][4] = {};

    #pragma unroll 1
    for (int c = 0; c < 6; c++) {
        const int wsel = c >> 1, kc = c & 1;
        const uint32_t wbuf = sb + ((c & 1) ? QW1 : QW0);

        if (c + 1 < 6) {
            const int nc = c + 1;
            const char* Wsrc = (const char*)(g_W16 + (nc >> 1) * 65536
                                             + (nc & 1) * 128 * DM);
            const uint32_t wdst = sb + ((nc & 1) ? QW1 : QW0);
            #pragma unroll
            for (int p = 0; p < 16; p++) {
                int q = p * 256 + t;
                int row = q >> 5, gr = q & 31;
                CP_ASYNC16(wdst + row * ASTR + gr * 16, Wsrc + row * 512 + gr * 16);
            }
            CP_COMMIT();
            CP_WAIT1();
        } else {
            CP_WAIT0();
        }
        __syncthreads();

        #pragma unroll
        for (int kk = 0; kk < 8; kk++) {
            uint32_t a[4][4];
            #pragma unroll
            for (int mi = 0; mi < 4; mi++)
                ldsm4(a[mi], abase + mi * 16 * ASTR + kc * 256 + kk * 32);
            #pragma unroll
            for (int np = 0; np < 4; np++) {
                uint32_t bb[4];
                ldsm4t(bb, wbuf + (uint32_t)(kk * 16) * ASTR + wb_lane + np * 32);
                #pragma unroll
                for (int mi = 0; mi < 4; mi++) {
                    mma16816(acc[mi][2 * np],     a[mi], bb[0], bb[1]);
                    mma16816(acc[mi][2 * np + 1], a[mi], bb[2], bb[3]);
                }
            }
        }

        if (kc == 1) {
            const float* bias = (const float*)(smem + QBIA + wsel * 1024);
            __half* outp = Os[wsel];
            #pragma unroll
            for (int mi = 0; mi < 4; mi++) {
                int r0 = 64 * wm2 + 16 * mi + gq;
                #pragma unroll
                for (int nt = 0; nt < 8; nt++) {
                    int col = 64 * wn2 + 8 * nt + 2 * tg;
                    float2 bv2 = *(const float2*)(bias + col);
                    *(uint32_t*)(outp + (size_t)(m0 + r0) * DM + col) =
                        pack_h2(acc[mi][nt][0] + bv2.x, acc[mi][nt][1] + bv2.y);
                    *(uint32_t*)(outp + (size_t)(m0 + r0 + 8) * DM + col) =
                        pack_h2(acc[mi][nt][2] + bv2.x, acc[mi][nt][3] + bv2.y);
                }
            }
            #pragma unroll
            for (int mi = 0; mi < 4; mi++)
                #pragma unroll
                for (int nt = 0; nt < 8; nt++)
                    #pragma unroll
                    for (int k2 = 0; k2 < 4; k2++)
                        acc[mi][nt][k2] = 0.0f;
        }
        __syncthreads();
    }
}

// ---------------------------------------------------------------------------
// Attention (R15, best verified ~242us): CTA = 128 q rows, 8 warps, TOK = 64.
// S-phase: 4 row-groups(32r) x 2 token-halves(32t); fragments double-buffered.
// P (128x64 fp16) roundtrips through smem.
// O-phase: 2 row-groups(64r) x 4 d-slices(64d); V frags double-buffered.
// Q pre-scaled by 2^-4 -> bare __expf.
// ---------------------------------------------------------------------------
#define TOK 64
#define NCHUNK (SEQ / TOK)       // 36
#define PSTR 144                 // P row stride (64h=128B + 16 pad)

#define AQ  0                        // Q  [128][528]   67584
#define AK0 (128 * ASTR)             // K buf0 [64][528]
#define AK1 (AK0 + 64 * ASTR)
#define AV0 (AK1 + 64 * ASTR)
#define AV1 (AV0 + 64 * ASTR)
#define AP  (AV1 + 64 * ASTR)        // P [128][144]
#define ARS (AP + 128 * PSTR)
#define ATT_SMEM (ARS + 1024)

__global__ __launch_bounds__(256, 1) void attn_mma(float* __restrict__ out)
{
    extern __shared__ char smem[];
    const uint32_t sb = smem_u32(smem);
    const int t = threadIdx.x, w = t >> 5, lane = t & 31;
    const int g = lane >> 2, tg = lane & 3;
    const int i8 = lane & 7, s1 = (lane >> 3) & 1, s2 = (lane >> 4) & 1;
    const int q4 = lane >> 3;

    const int qt = blockIdx.x, b = blockIdx.y;
    const __half* Qg = g_Q + ((size_t)b * SEQ + qt * 128) * DM;
    const __half* Kg = g_K + (size_t)b * SEQ * DM;
    const __half* Vg = g_V + (size_t)b * SEQ * DM;

    #pragma unroll
    for (int p = 0; p < 16; p++) {
        int q = p * 256 + t;
        int row = q >> 5, gr = q & 31;
        CP_ASYNC16(sb + AQ + row * ASTR + gr * 16,
                   (const char*)Qg + row * 512 + gr * 16);
    }
    #pragma unroll
    for (int p = 0; p < 8; p++) {
        int q = p * 256 + t;
        int row = q >> 5, gr = q & 31;
        CP_ASYNC16(sb + AK0 + row * ASTR + gr * 16,
                   (const char*)Kg + row * 512 + gr * 16);
        CP_ASYNC16(sb + AV0 + row * ASTR + gr * 16,
                   (const char*)Vg + row * 512 + gr * 16);
    }
    CP_COMMIT();

    const int wm = w & 3, wn = w >> 2;
    const int wm2 = w & 1, wn2 = w >> 1;

    const uint32_t qa_base = sb + AQ + (32 * wm + i8 + s1 * 8) * ASTR + s2 * 16;
    const uint32_t kb_lane = (uint32_t)(((q4 >> 1) * 8 + i8) * ASTR + (q4 & 1) * 16);
    const uint32_t vb_lane = (uint32_t)(((q4 & 1) * 8 + i8) * ASTR + (q4 >> 1) * 16);
    const uint32_t pa_base = sb + AP + (64 * wm2 + i8 + s1 * 8) * PSTR + s2 * 16;

    float oc[4][8][4] = {};
    float rsp[2][2] = {};

    for (int kt = 0; kt < NCHUNK; kt++) {
        CP_WAIT0();
        __syncthreads();
        const uint32_t kbuf = sb + (kt & 1 ? AK1 : AK0);
        const uint32_t vbuf = sb + (kt & 1 ? AV1 : AV0);

        if (kt + 1 < NCHUNK) {
            const __half* Kt = Kg + (size_t)(kt + 1) * TOK * DM;
            const __half* Vt = Vg + (size_t)(kt + 1) * TOK * DM;
            const uint32_t kdst = sb + ((kt + 1) & 1 ? AK1 : AK0);
            const uint32_t vdst = sb + ((kt + 1) & 1 ? AV1 : AV0);
            #pragma unroll
            for (int p = 0; p < 8; p++) {
                int q = p * 256 + t;
                int row = q >> 5, gr = q & 31;
                CP_ASYNC16(kdst + row * ASTR + gr * 16,
                           (const char*)Kt + row * 512 + gr * 16);
                CP_ASYNC16(vdst + row * ASTR + gr * 16,
                           (const char*)Vt + row * 512 + gr * 16);
            }
        }
        CP_COMMIT();

        // ---- S = Q K^T (pipelined fragments) ----
        const uint32_t kbA = kbuf + (uint32_t)(32 * wn) * ASTR + kb_lane;
        const uint32_t kbB = kbuf + (uint32_t)(32 * wn + 16) * ASTR + kb_lane;
        float sc[2][4][4] = {};
        uint32_t a0[2][4], a1[2][4], f0[2][4], f1[2][4];
        ldsm4(a0[0], qa_base);
        ldsm4(a1[0], qa_base + 16 * ASTR);
        ldsm4(f0[0], kbA);
        ldsm4(f1[0], kbB);
        #pragma unroll
        for (int kk = 0; kk < 16; kk++) {
            const int cur = kk & 1, nxt = cur ^ 1;
            if (kk < 15) {
                ldsm4(a0[nxt], qa_base + (kk + 1) * 32);
                ldsm4(a1[nxt], qa_base + 16 * ASTR + (kk + 1) * 32);
                ldsm4(f0[nxt], kbA + (kk + 1) * 32);
                ldsm4(f1[nxt], kbB + (kk + 1) * 32);
            }
            mma16816(sc[0][0], a0[cur], f0[cur][0], f0[cur][1]);
            mma16816(sc[1][0], a1[cur], f0[cur][0], f0[cur][1]);
            mma16816(sc[0][1], a0[cur], f0[cur][2], f0[cur][3]);
            mma16816(sc[1][1], a1[cur], f0[cur][2], f0[cur][3]);
            mma16816(sc[0][2], a0[cur], f1[cur][0], f1[cur][1]);
            mma16816(sc[1][2], a1[cur], f1[cur][0], f1[cur][1]);
            mma16816(sc[0][3], a0[cur], f1[cur][2], f1[cur][3]);
            mma16816(sc[1][3], a1[cur], f1[cur][2], f1[cur][3]);
        }

        // ---- softmax (bare exp; Q pre-scaled) ----
        #pragma unroll
        for (int mi = 0; mi < 2; mi++) {
            int rowA = 32 * wm + 16 * mi + g;
            char* pw = smem + AP + rowA * PSTR + (16 * wn + tg) * 4;
            #pragma unroll
            for (int nt = 0; nt < 4; nt++) {
                float p00 = __expf(sc[mi][nt][0]);
                float p01 = __expf(sc[mi][nt][1]);
                float p10 = __expf(sc[mi][nt][2]);
                float p11 = __expf(sc[mi][nt][3]);
                rsp[mi][0] += p00 + p01;
                rsp[mi][1] += p10 + p11;
                *(uint32_t*)(pw + nt * 16)            = pack_h2(p00, p01);
                *(uint32_t*)(pw + nt * 16 + 8 * PSTR) = pack_h2(p10, p11);
            }
        }
        __syncthreads();

        // ---- O += P V (V frags double-buffered) ----
        #pragma unroll
        for (int kk2 = 0; kk2 < 4; kk2++) {
            const uint32_t vrow = vbuf + (uint32_t)(kk2 * 16) * ASTR + vb_lane
                                  + 128 * wn2;
            uint32_t pa[4][4];
            #pragma unroll
            for (int mi = 0; mi < 4; mi++)
                ldsm4(pa[mi], pa_base + mi * 16 * PSTR + kk2 * 32);
            uint32_t vb[2][4];
            ldsm4t(vb[0], vrow);
            #pragma unroll
            for (int np = 0; np < 4; np++) {
                const int cur = np & 1, nxt = cur ^ 1;
                if (np < 3) ldsm4t(vb[nxt], vrow + (np + 1) * 32);
                #pragma unroll
                for (int mi = 0; mi < 4; mi++) {
                    mma16816(oc[mi][2 * np],     pa[mi], vb[cur][0], vb[cur][1]);
                    mma16816(oc[mi][2 * np + 1], pa[mi], vb[cur][2], vb[cur][3]);
                }
            }
        }
    }

    // ---- rowsum finalize ----
    float* rs = (float*)(smem + ARS);
    #pragma unroll
    for (int mi = 0; mi < 2; mi++)
        #pragma unroll
        for (int h = 0; h < 2; h++) {
            float v = rsp[mi][h];
            v += __shfl_xor_sync(0xffffffffu, v, 1);
            v += __shfl_xor_sync(0xffffffffu, v, 2);
            if (tg == 0) rs[(32 * wm + 16 * mi + g + 8 * h) * 2 + wn] = v;
        }
    __syncthreads();

    // ---- output ----
    float* ob = out + ((size_t)b * SEQ + qt * 128) * DM;
    #pragma unroll
    for (int mi = 0; mi < 4; mi++) {
        int r0 = 64 * wm2 + 16 * mi + g;
        float inv0 = 1.0f / (rs[r0 * 2] + rs[r0 * 2 + 1]);
        float inv1 = 1.0f / (rs[(r0 + 8) * 2] + rs[(r0 + 8) * 2 + 1]);
        #pragma unroll
        for (int nt = 0; nt < 8; nt++) {
            int col = 64 * wn2 + 8 * nt + 2 * tg;
            *(float2*)(ob + (size_t)r0 * DM + col) =
                make_float2(oc[mi][nt][0] * inv0, oc[mi][nt][1] * inv0);
            *(float2*)(ob + (size_t)(r0 + 8) * DM + col) =
                make_float2(oc[mi][nt][2] * inv1, oc[mi][nt][3] * inv1);
        }
    }
}

extern "C" void kernel_launch(void* const* d_in, const int* in_sizes, int n_in,
                              void* d_out, int out_size)
{
    const float* x   = (const float*)d_in[0];
    const float* wq  = (const float*)d_in[1];
    const float* bq  = (const float*)d_in[2];
    const float* wk  = (const float*)d_in[3];
    const float* bk  = (const float*)d_in[4];
    const float* wv  = (const float*)d_in[5];
    const float* bv  = (const float*)d_in[6];
    const float* pos = (const float*)d_in[7];
    float* out = (float*)d_out;

    cudaFuncSetAttribute(qkv_fused5, cudaFuncAttributeMaxDynamicSharedMemorySize,
                         QKV_SMEM);
    cudaFuncSetAttribute(attn_mma, cudaFuncAttributeMaxDynamicSharedMemorySize,
                         ATT_SMEM);

    prep<<<XH_BLOCKS2 + 48, 256>>>(x, pos, wq, wk, wv);
    qkv_fused5<<<(NB * SEQ) / 128, 256, QKV_SMEM>>>(bq, bk, bv);
    attn_mma<<<dim3(SEQ / 128, NB), 256, ATT_SMEM>>>(out);
}